// round 14
// baseline (speedup 1.0000x reference)
#include <cuda_runtime.h>
#include <cuda_fp16.h>
#include <cstdint>

// ---------------------------------------------------------------- dims
#define B_  128
#define T_  254
#define D_  768
#define H_  1024
#define M_  (B_ * T_)      // 32512
#define K1_ (2 * D_)       // 1536
#define N1_ (2 * H_)       // 2048
#define K2_ N1_            // 2048
#define N2_ H_             // 1024

// ---------------------------------------------------------------- scratch
__device__ __half g_feats[(size_t)M_ * K1_];   // fp16 features [M,1536]
__device__ __half g_h1[(size_t)M_ * N1_];      // fp16 h1 [M,2048]
__device__ __half g_w1t[(size_t)N1_ * K1_];    // W1^T fp16 [N,K]
__device__ __half g_w2t[(size_t)N2_ * K2_];    // W2^T fp16 [N,K]

// ---------------------------------------------------------------- helpers
__device__ __forceinline__ uint32_t smem_u32(const void* p) {
    uint32_t a;
    asm("{ .reg .u64 t; cvta.to.shared.u64 t, %1; cvt.u32.u64 %0, t; }"
        : "=r"(a) : "l"(p));
    return a;
}

#define CP16(dst, src) \
    asm volatile("cp.async.cg.shared.global [%0], [%1], 16;" \
                 :: "r"(dst), "l"(src) : "memory")

#define LDSM4(r, addr)                                                        \
    asm volatile("ldmatrix.sync.aligned.m8n8.x4.shared.b16 {%0,%1,%2,%3}, [%4];" \
        : "=r"((r)[0]), "=r"((r)[1]), "=r"((r)[2]), "=r"((r)[3]) : "r"(addr))

#define MMA16816(c, a, b0, b1)                                                \
    asm volatile("mma.sync.aligned.m16n8k16.row.col.f32.f16.f16.f32 "         \
        "{%0,%1,%2,%3},{%4,%5,%6,%7},{%8,%9},{%0,%1,%2,%3};"                  \
        : "+f"((c)[0]), "+f"((c)[1]), "+f"((c)[2]), "+f"((c)[3])              \
        : "r"((a)[0]), "r"((a)[1]), "r"((a)[2]), "r"((a)[3]),                 \
          "r"(b0), "r"(b1))

// ---------------------------------------------------------------- shared transpose helper
__device__ __forceinline__ void do_transpose(const float* __restrict__ W,
                                             __half* __restrict__ WT,
                                             int K, int N, int bx, int by, int tid) {
    __shared__ float tile[32][33];
    int k0 = bx * 32, n0 = by * 32;
    int tx = tid & 31, ty = tid >> 5;                  // (32, 8)
    #pragma unroll
    for (int j = 0; j < 32; j += 8)
        tile[ty + j][tx] = W[(size_t)(k0 + ty + j) * N + n0 + tx];
    __syncthreads();
    #pragma unroll
    for (int j = 0; j < 32; j += 8)
        WT[(size_t)(n0 + ty + j) * K + k0 + tx] = __float2half_rn(tile[tx][ty + j]);
}

// ---------------------------------------------------------------- fused setup
// [0, 384)     prefix scan, T split in two halves
// [384, +3072) transpose W1 -> g_w1t
#define PFX_BLKS   (B_ * D_ / 2 / 256)                 // 192 per half
#define T1_BX      (K1_ / 32)                          // 48
#define T1_BLKS    (T1_BX * (N1_ / 32))                // 3072
#define SETUP_BLKS (2 * PFX_BLKS + T1_BLKS)            // 3456
#define T_SPLIT 128

__global__ __launch_bounds__(256) void setup_kernel(
    const float* __restrict__ h, const float* __restrict__ W1)
{
    int blk = blockIdx.x;
    int tid = threadIdx.x;

    if (blk < 2 * PFX_BLKS) {
        int half = blk >= PFX_BLKS;
        int idx = (blk - half * PFX_BLKS) * 256 + tid;     // over B_*D_/2
        int b  = idx / (D_ / 2);
        int d2 = idx - b * (D_ / 2);
        const float2* hp = (const float2*)(h + (size_t)b * T_ * D_) + d2;
        __half2* fm = (__half2*)(g_feats + (size_t)b * T_ * K1_) + d2;
        __half2* fx = (__half2*)(g_feats + (size_t)b * T_ * K1_ + D_) + d2;
        float r0 = 0.0f, r1 = 0.0f;
        int t0 = half ? T_SPLIT : 0;
        int t1 = half ? T_ : T_SPLIT;
        if (half) {
            #pragma unroll 1
            for (int t = 0; t < T_SPLIT; t += 8) {
                float2 x[8];
                #pragma unroll
                for (int j = 0; j < 8; ++j) x[j] = hp[(size_t)(t + j) * (D_ / 2)];
                #pragma unroll
                for (int j = 0; j < 8; ++j) { r0 += x[j].x; r1 += x[j].y; }
            }
        }
        int t = t0;
        #pragma unroll 1
        for (; t + 4 <= t1; t += 4) {
            float2 x0 = hp[(size_t)(t + 0) * (D_ / 2)];
            float2 x1 = hp[(size_t)(t + 1) * (D_ / 2)];
            float2 x2 = hp[(size_t)(t + 2) * (D_ / 2)];
            float2 x3 = hp[(size_t)(t + 3) * (D_ / 2)];
            float i0 = 1.0f / (float)(t + 0 > 1 ? t + 0 : 1);
            float i1 = 1.0f / (float)(t + 1 > 1 ? t + 1 : 1);
            float i2 = 1.0f / (float)(t + 2);
            float i3 = 1.0f / (float)(t + 3);
            fm[(size_t)(t + 0) * (K1_ / 2)] = __floats2half2_rn(r0 * i0, r1 * i0);
            fx[(size_t)(t + 0) * (K1_ / 2)] = __floats2half2_rn(x0.x, x0.y);
            r0 += x0.x; r1 += x0.y;
            fm[(size_t)(t + 1) * (K1_ / 2)] = __floats2half2_rn(r0 * i1, r1 * i1);
            fx[(size_t)(t + 1) * (K1_ / 2)] = __floats2half2_rn(x1.x, x1.y);
            r0 += x1.x; r1 += x1.y;
            fm[(size_t)(t + 2) * (K1_ / 2)] = __floats2half2_rn(r0 * i2, r1 * i2);
            fx[(size_t)(t + 2) * (K1_ / 2)] = __floats2half2_rn(x2.x, x2.y);
            r0 += x2.x; r1 += x2.y;
            fm[(size_t)(t + 3) * (K1_ / 2)] = __floats2half2_rn(r0 * i3, r1 * i3);
            fx[(size_t)(t + 3) * (K1_ / 2)] = __floats2half2_rn(x3.x, x3.y);
            r0 += x3.x; r1 += x3.y;
        }
        for (; t < t1; ++t) {
            float2 x = hp[(size_t)t * (D_ / 2)];
            float inv = 1.0f / (float)(t > 1 ? t : 1);
            fm[(size_t)t * (K1_ / 2)] = __floats2half2_rn(r0 * inv, r1 * inv);
            fx[(size_t)t * (K1_ / 2)] = __floats2half2_rn(x.x, x.y);
            r0 += x.x; r1 += x.y;
        }
    } else {
        int t = blk - 2 * PFX_BLKS;
        do_transpose(W1, g_w1t, K1_, N1_, t % T1_BX, t / T1_BX, tid);
    }
}

// ---------------------------------------------------------------- fp16 tensor GEMM
// Tile 128x128, 8 warps (4M x 2N), warp tile 32x64, 3-stage cp.async, 2 CTAs/SM.
// Full A+B fragment double-buffering across kk: per iteration prefetch the
// next kk's fragments, then issue MMAs on the current ones.
#define BM 128
#define BN 128
#define BKH 64
#define STAGES 3
#define A_BYTES (BM * 128)
#define STAGE_BYTES (A_BYTES + BN * 128)      // 32768
#define SMEM_TOTAL (STAGES * STAGE_BYTES)     // 98304

#define G1_NX      (N1_ / BN)                 // 16
#define G1_BLKS    (G1_NX * (M_ / BM))        // 4064
#define T2_BX      (K2_ / 32)                 // 64
#define T2_BLKS    (T2_BX * (N2_ / 32))       // 2048
#define INIT_BLKS  ((M_ + 255) / 256)         // 127
#define G1_TOTAL   (G1_BLKS + T2_BLKS + INIT_BLKS)

template <bool FUSE_HEAD, bool SIDE>
__global__ __launch_bounds__(256, 2) void gemm_fp16(
    const __half* __restrict__ A, const __half* __restrict__ BT,
    const float* __restrict__ bias, __half* __restrict__ C,
    const float* __restrict__ W3, float* __restrict__ out,
    int K, int N,
    const float* __restrict__ Wside, const float* __restrict__ b3)
{
    extern __shared__ char smem[];
    const int tid = threadIdx.x;

    int bx, by;
    if (SIDE) {
        int bid = blockIdx.x;
        if (bid >= G1_BLKS) {
            int t = bid - G1_BLKS;
            if (t < T2_BLKS) {
                do_transpose(Wside, g_w2t, K2_, N2_, t % T2_BX, t / T2_BX, tid);
            } else {
                int i = (t - T2_BLKS) * 256 + tid;
                if (i < M_) out[i] = b3[0];
            }
            return;
        }
        bx = bid % G1_NX;
        by = bid / G1_NX;
    } else {
        bx = blockIdx.x;
        by = blockIdx.y;
    }

    const uint32_t sb = smem_u32(smem);
    const int warp = tid >> 5;
    const int lane = tid & 31;
    const int wm = warp & 3;          // 4 warps along M  (32 rows each)
    const int wn = warp >> 2;         // 2 warps along N  (64 cols each)
    const int bm = by * BM;
    const int bn = bx * BN;
    const int KC = K / BKH;
    const int lq = lane >> 3;         // quad 0..3
    const int lr = lane & 7;          // row in quad

    float acc[2][8][4];
    #pragma unroll
    for (int i = 0; i < 2; ++i)
        #pragma unroll
        for (int j = 0; j < 8; ++j)
            #pragma unroll
            for (int c = 0; c < 4; ++c) acc[i][j][c] = 0.0f;

    // Per-warp LDSM base addresses (swizzled) — precomputed once.
    // A frag (ma, kk): row = wm*32 + ma*16 + (lq&1)*8 + lr; chunk = kk*2 + (lq>>1)
    // B frag (p, kk):  row = wn*64 + p*16 + (lq>>1)*8 + lr; chunk = kk*2 + (lq&1)
    const int arow0 = wm * 32 + (lq & 1) * 8 + lr;
    const int brow0 = wn * 64 + (lq >> 1) * 8 + lr;

    auto load_stage = [&](int q, int s) {
        uint32_t stA = sb + s * STAGE_BYTES;
        uint32_t stB = stA + A_BYTES;
        #pragma unroll
        for (int i = 0; i < 4; ++i) {
            int c = i * 256 + tid;
            int r = c >> 3, col = c & 7;
            const __half* src = A + (size_t)(bm + r) * K + q * BKH + col * 8;
            CP16(stA + r * 128 + ((col ^ (r & 7)) * 16), src);
        }
        #pragma unroll
        for (int i = 0; i < 4; ++i) {
            int c = i * 256 + tid;
            int r = c >> 3, col = c & 7;
            const __half* src = BT + (size_t)(bn + r) * K + q * BKH + col * 8;
            CP16(stB + r * 128 + ((col ^ (r & 7)) * 16), src);
        }
    };

    #pragma unroll
    for (int s = 0; s < STAGES - 1; ++s) {
        load_stage(s, s);
        asm volatile("cp.async.commit_group;" ::: "memory");
    }

    for (int q = 0; q < KC; ++q) {
        asm volatile("cp.async.wait_group %0;" :: "n"(STAGES - 2) : "memory");
        __syncthreads();

        int pre = q + STAGES - 1;
        if (pre < KC) load_stage(pre, pre % STAGES);
        asm volatile("cp.async.commit_group;" ::: "memory");

        uint32_t stA = sb + (q % STAGES) * STAGE_BYTES;
        uint32_t stB = stA + A_BYTES;

        // --- full fragment pipeline: A and B double-buffered across kk
        uint32_t afr[2][2][4], bfr[2][4][4];
        #pragma unroll
        for (int ma = 0; ma < 2; ++ma) {
            int row = arow0 + ma * 16;
            LDSM4(afr[0][ma], stA + row * 128 + (((lq >> 1) ^ (row & 7)) * 16));
        }
        #pragma unroll
        for (int p = 0; p < 4; ++p) {
            int row = brow0 + p * 16;
            LDSM4(bfr[0][p], stB + row * 128 + (((lq & 1) ^ (row & 7)) * 16));
        }

        #pragma unroll
        for (int kk = 0; kk < 4; ++kk) {
            const int cur = kk & 1, nxt = cur ^ 1;
            if (kk < 3) {
                #pragma unroll
                for (int ma = 0; ma < 2; ++ma) {
                    int row = arow0 + ma * 16;
                    int ch  = (kk + 1) * 2 + (lq >> 1);
                    LDSM4(afr[nxt][ma], stA + row * 128 + ((ch ^ (row & 7)) * 16));
                }
                #pragma unroll
                for (int p = 0; p < 4; ++p) {
                    int row = brow0 + p * 16;
                    int ch  = (kk + 1) * 2 + (lq & 1);
                    LDSM4(bfr[nxt][p], stB + row * 128 + ((ch ^ (row & 7)) * 16));
                }
            }
            #pragma unroll
            for (int ma = 0; ma < 2; ++ma)
                #pragma unroll
                for (int p = 0; p < 4; ++p) {
                    MMA16816(acc[ma][2 * p],     afr[cur][ma], bfr[cur][p][0], bfr[cur][p][1]);
                    MMA16816(acc[ma][2 * p + 1], afr[cur][ma], bfr[cur][p][2], bfr[cur][p][3]);
                }
        }
    }

    if (!FUSE_HEAD) {
        #pragma unroll
        for (int ma = 0; ma < 2; ++ma) {
            int row = bm + wm * 32 + ma * 16 + (lane >> 2);
            #pragma unroll
            for (int nb = 0; nb < 8; ++nb) {
                int col = bn + wn * 64 + nb * 8 + (lane & 3) * 2;
                float bv0 = bias[col], bv1 = bias[col + 1];
                float v0 = fmaxf(acc[ma][nb][0] + bv0, 0.0f);
                float v1 = fmaxf(acc[ma][nb][1] + bv1, 0.0f);
                float v2 = fmaxf(acc[ma][nb][2] + bv0, 0.0f);
                float v3 = fmaxf(acc[ma][nb][3] + bv1, 0.0f);
                *(__half2*)(C + (size_t)row * N + col)       = __floats2half2_rn(v0, v1);
                *(__half2*)(C + (size_t)(row + 8) * N + col) = __floats2half2_rn(v2, v3);
            }
        }
    } else {
        float p0 = 0.f, p1 = 0.f, p2 = 0.f, p3 = 0.f;
        #pragma unroll
        for (int nb = 0; nb < 8; ++nb) {
            int col = bn + wn * 64 + nb * 8 + (lane & 3) * 2;
            float bv0 = bias[col], bv1 = bias[col + 1];
            float w0 = W3[col],    w1 = W3[col + 1];
            p0 += fmaxf(acc[0][nb][0] + bv0, 0.f) * w0 + fmaxf(acc[0][nb][1] + bv1, 0.f) * w1;
            p1 += fmaxf(acc[0][nb][2] + bv0, 0.f) * w0 + fmaxf(acc[0][nb][3] + bv1, 0.f) * w1;
            p2 += fmaxf(acc[1][nb][0] + bv0, 0.f) * w0 + fmaxf(acc[1][nb][1] + bv1, 0.f) * w1;
            p3 += fmaxf(acc[1][nb][2] + bv0, 0.f) * w0 + fmaxf(acc[1][nb][3] + bv1, 0.f) * w1;
        }
        #pragma unroll
        for (int o = 1; o <= 2; o <<= 1) {
            p0 += __shfl_xor_sync(0xffffffffu, p0, o);
            p1 += __shfl_xor_sync(0xffffffffu, p1, o);
            p2 += __shfl_xor_sync(0xffffffffu, p2, o);
            p3 += __shfl_xor_sync(0xffffffffu, p3, o);
        }
        __syncthreads();                 // mainloop smem dead -> reuse
        float* red = (float*)smem;       // [2][128]
        if ((lane & 3) == 0) {
            int rl = wm * 32 + (lane >> 2);
            red[wn * 128 + rl]      = p0;
            red[wn * 128 + rl + 8]  = p1;
            red[wn * 128 + rl + 16] = p2;
            red[wn * 128 + rl + 24] = p3;
        }
        __syncthreads();
        if (tid < 128)
            atomicAdd(&out[bm + tid], red[tid] + red[128 + tid]);
    }
}

// ---------------------------------------------------------------- launcher
extern "C" void kernel_launch(void* const* d_in, const int* in_sizes, int n_in,
                              void* d_out, int out_size) {
    const float* h  = (const float*)d_in[0];
    const float* W1 = (const float*)d_in[1];
    const float* b1 = (const float*)d_in[2];
    const float* W2 = (const float*)d_in[3];
    const float* b2 = (const float*)d_in[4];
    const float* W3 = (const float*)d_in[5];
    const float* b3 = (const float*)d_in[6];
    float* out = (float*)d_out;

    __half *feats, *h1, *w1t, *w2t;
    cudaGetSymbolAddress((void**)&feats, g_feats);
    cudaGetSymbolAddress((void**)&h1,    g_h1);
    cudaGetSymbolAddress((void**)&w1t,   g_w1t);
    cudaGetSymbolAddress((void**)&w2t,   g_w2t);

    cudaFuncSetAttribute((const void*)gemm_fp16<false, true>,
        cudaFuncAttributeMaxDynamicSharedMemorySize, SMEM_TOTAL);
    cudaFuncSetAttribute((const void*)gemm_fp16<true, false>,
        cudaFuncAttributeMaxDynamicSharedMemorySize, SMEM_TOTAL);

    // launch 0: fused setup (split prefix + transpose W1)
    setup_kernel<<<SETUP_BLKS, 256>>>(h, W1);

    // launch 1: h1 = relu(feats @ W1 + b1) -> fp16
    //           + trailing blocks: transpose W2 -> g_w2t, out = b3
    gemm_fp16<false, true><<<G1_TOTAL, 256, SMEM_TOTAL>>>(
        feats, w1t, b1, h1, nullptr, out, K1_, N1_, W2, b3);

    // launch 2: out += relu(h1 @ W2 + b2) @ W3   (head fused)
    gemm_fp16<true, false><<<dim3(N2_ / BN, M_ / BM), 256, SMEM_TOTAL>>>(
        h1, w2t, b2, nullptr, W3, out, K2_, N2_, nullptr, nullptr);
}

// round 15
// speedup vs baseline: 1.0604x; 1.0604x over previous
#include <cuda_runtime.h>
#include <cuda_fp16.h>
#include <cstdint>

// ---------------------------------------------------------------- dims
#define B_  128
#define T_  254
#define D_  768
#define H_  1024
#define M_  (B_ * T_)      // 32512
#define K1_ (2 * D_)       // 1536
#define N1_ (2 * H_)       // 2048
#define K2_ N1_            // 2048
#define N2_ H_             // 1024

// ---------------------------------------------------------------- scratch
__device__ __half g_feats[(size_t)M_ * K1_];   // fp16 features [M,1536]
__device__ __half g_h1[(size_t)M_ * N1_];      // fp16 h1 [M,2048]
__device__ __half g_w1t[(size_t)N1_ * K1_];    // W1^T fp16 [N,K]
__device__ __half g_w2t[(size_t)N2_ * K2_];    // W2^T fp16 [N,K]

// ---------------------------------------------------------------- helpers
__device__ __forceinline__ uint32_t smem_u32(const void* p) {
    uint32_t a;
    asm("{ .reg .u64 t; cvta.to.shared.u64 t, %1; cvt.u32.u64 %0, t; }"
        : "=r"(a) : "l"(p));
    return a;
}

#define CP16(dst, src) \
    asm volatile("cp.async.cg.shared.global [%0], [%1], 16;" \
                 :: "r"(dst), "l"(src) : "memory")

#define LDSM4(r, addr)                                                        \
    asm volatile("ldmatrix.sync.aligned.m8n8.x4.shared.b16 {%0,%1,%2,%3}, [%4];" \
        : "=r"((r)[0]), "=r"((r)[1]), "=r"((r)[2]), "=r"((r)[3]) : "r"(addr))

#define MMA16816(c, a, b0, b1)                                                \
    asm volatile("mma.sync.aligned.m16n8k16.row.col.f32.f16.f16.f32 "         \
        "{%0,%1,%2,%3},{%4,%5,%6,%7},{%8,%9},{%0,%1,%2,%3};"                  \
        : "+f"((c)[0]), "+f"((c)[1]), "+f"((c)[2]), "+f"((c)[3])              \
        : "r"((a)[0]), "r"((a)[1]), "r"((a)[2]), "r"((a)[3]),                 \
          "r"(b0), "r"(b1))

// ---------------------------------------------------------------- shared transpose helper
// Works for any blockDim that is a multiple of 32.
__device__ __forceinline__ void do_transpose(const float* __restrict__ W,
                                             __half* __restrict__ WT,
                                             int K, int N, int bx, int by, int tid) {
    __shared__ float tile[32][33];
    int k0 = bx * 32, n0 = by * 32;
    int tx = tid & 31, ty = tid >> 5;
    int nty = blockDim.x >> 5;
    for (int j = ty; j < 32; j += nty)
        tile[j][tx] = W[(size_t)(k0 + j) * N + n0 + tx];
    __syncthreads();
    for (int j = ty; j < 32; j += nty)
        WT[(size_t)(n0 + j) * K + k0 + tx] = __float2half_rn(tile[tx][j]);
}

// ---------------------------------------------------------------- fused setup
// [0, 384)     prefix scan, T split in two halves
// [384, +3072) transpose W1 -> g_w1t
#define PFX_BLKS   (B_ * D_ / 2 / 256)                 // 192 per half
#define T1_BX      (K1_ / 32)                          // 48
#define T1_BLKS    (T1_BX * (N1_ / 32))                // 3072
#define SETUP_BLKS (2 * PFX_BLKS + T1_BLKS)            // 3456
#define T_SPLIT 128

__global__ __launch_bounds__(256) void setup_kernel(
    const float* __restrict__ h, const float* __restrict__ W1)
{
    int blk = blockIdx.x;
    int tid = threadIdx.x;

    if (blk < 2 * PFX_BLKS) {
        int half = blk >= PFX_BLKS;
        int idx = (blk - half * PFX_BLKS) * 256 + tid;     // over B_*D_/2
        int b  = idx / (D_ / 2);
        int d2 = idx - b * (D_ / 2);
        const float2* hp = (const float2*)(h + (size_t)b * T_ * D_) + d2;
        __half2* fm = (__half2*)(g_feats + (size_t)b * T_ * K1_) + d2;
        __half2* fx = (__half2*)(g_feats + (size_t)b * T_ * K1_ + D_) + d2;
        float r0 = 0.0f, r1 = 0.0f;
        int t0 = half ? T_SPLIT : 0;
        int t1 = half ? T_ : T_SPLIT;
        if (half) {
            #pragma unroll 1
            for (int t = 0; t < T_SPLIT; t += 8) {
                float2 x[8];
                #pragma unroll
                for (int j = 0; j < 8; ++j) x[j] = hp[(size_t)(t + j) * (D_ / 2)];
                #pragma unroll
                for (int j = 0; j < 8; ++j) { r0 += x[j].x; r1 += x[j].y; }
            }
        }
        int t = t0;
        #pragma unroll 1
        for (; t + 4 <= t1; t += 4) {
            float2 x0 = hp[(size_t)(t + 0) * (D_ / 2)];
            float2 x1 = hp[(size_t)(t + 1) * (D_ / 2)];
            float2 x2 = hp[(size_t)(t + 2) * (D_ / 2)];
            float2 x3 = hp[(size_t)(t + 3) * (D_ / 2)];
            float i0 = 1.0f / (float)(t + 0 > 1 ? t + 0 : 1);
            float i1 = 1.0f / (float)(t + 1 > 1 ? t + 1 : 1);
            float i2 = 1.0f / (float)(t + 2);
            float i3 = 1.0f / (float)(t + 3);
            fm[(size_t)(t + 0) * (K1_ / 2)] = __floats2half2_rn(r0 * i0, r1 * i0);
            fx[(size_t)(t + 0) * (K1_ / 2)] = __floats2half2_rn(x0.x, x0.y);
            r0 += x0.x; r1 += x0.y;
            fm[(size_t)(t + 1) * (K1_ / 2)] = __floats2half2_rn(r0 * i1, r1 * i1);
            fx[(size_t)(t + 1) * (K1_ / 2)] = __floats2half2_rn(x1.x, x1.y);
            r0 += x1.x; r1 += x1.y;
            fm[(size_t)(t + 2) * (K1_ / 2)] = __floats2half2_rn(r0 * i2, r1 * i2);
            fx[(size_t)(t + 2) * (K1_ / 2)] = __floats2half2_rn(x2.x, x2.y);
            r0 += x2.x; r1 += x2.y;
            fm[(size_t)(t + 3) * (K1_ / 2)] = __floats2half2_rn(r0 * i3, r1 * i3);
            fx[(size_t)(t + 3) * (K1_ / 2)] = __floats2half2_rn(x3.x, x3.y);
            r0 += x3.x; r1 += x3.y;
        }
        for (; t < t1; ++t) {
            float2 x = hp[(size_t)t * (D_ / 2)];
            float inv = 1.0f / (float)(t > 1 ? t : 1);
            fm[(size_t)t * (K1_ / 2)] = __floats2half2_rn(r0 * inv, r1 * inv);
            fx[(size_t)t * (K1_ / 2)] = __floats2half2_rn(x.x, x.y);
            r0 += x.x; r1 += x.y;
        }
    } else {
        int t = blk - 2 * PFX_BLKS;
        do_transpose(W1, g_w1t, K1_, N1_, t % T1_BX, t / T1_BX, tid);
    }
}

// ---------------------------------------------------------------- fp16 tensor GEMM
// Tile 128x128, 4 warps (2M x 2N), warp tile 64x64, 3-stage cp.async, 2 CTAs/SM.
// 64x64 warp tile cuts LDSM bytes/MAC by 33% vs 32x64 — the smem crossbar was
// the binding constraint (125 of 128 B/cyc); now ~94 B/cyc, HMMA-bound.
// B fragments double-buffered across kk (A in place, per R13 reg budget).
#define BM 128
#define BN 128
#define BKH 64
#define STAGES 3
#define THREADS 128
#define A_BYTES (BM * 128)
#define STAGE_BYTES (A_BYTES + BN * 128)      // 32768
#define SMEM_TOTAL (STAGES * STAGE_BYTES)     // 98304

#define G1_NX      (N1_ / BN)                 // 16
#define G1_BLKS    (G1_NX * (M_ / BM))        // 4064
#define T2_BX      (K2_ / 32)                 // 64
#define T2_BLKS    (T2_BX * (N2_ / 32))       // 2048
#define INIT_BLKS  ((M_ + THREADS - 1) / THREADS)   // 254
#define G1_TOTAL   (G1_BLKS + T2_BLKS + INIT_BLKS)

template <bool FUSE_HEAD, bool SIDE>
__global__ __launch_bounds__(THREADS, 2) void gemm_fp16(
    const __half* __restrict__ A, const __half* __restrict__ BT,
    const float* __restrict__ bias, __half* __restrict__ C,
    const float* __restrict__ W3, float* __restrict__ out,
    int K, int N,
    const float* __restrict__ Wside, const float* __restrict__ b3)
{
    extern __shared__ char smem[];
    const int tid = threadIdx.x;

    int bx, by;
    if (SIDE) {
        int bid = blockIdx.x;
        if (bid >= G1_BLKS) {
            int t = bid - G1_BLKS;
            if (t < T2_BLKS) {
                do_transpose(Wside, g_w2t, K2_, N2_, t % T2_BX, t / T2_BX, tid);
            } else {
                int i = (t - T2_BLKS) * THREADS + tid;
                if (i < M_) out[i] = b3[0];
            }
            return;
        }
        bx = bid % G1_NX;
        by = bid / G1_NX;
    } else {
        bx = blockIdx.x;
        by = blockIdx.y;
    }

    const uint32_t sb = smem_u32(smem);
    const int warp = tid >> 5;
    const int lane = tid & 31;
    const int wm = warp & 1;          // 2 warps along M (64 rows each)
    const int wn = warp >> 1;         // 2 warps along N (64 cols each)
    const int bm = by * BM;
    const int bn = bx * BN;
    const int KC = K / BKH;
    const int lq = lane >> 3;         // quad 0..3
    const int lr = lane & 7;          // row in quad

    float acc[4][8][4];
    #pragma unroll
    for (int i = 0; i < 4; ++i)
        #pragma unroll
        for (int j = 0; j < 8; ++j)
            #pragma unroll
            for (int c = 0; c < 4; ++c) acc[i][j][c] = 0.0f;

    const int arow0 = wm * 64 + (lq & 1) * 8 + lr;    // + mf*16
    const int brow0 = wn * 64 + (lq >> 1) * 8 + lr;   // + p*16

    auto load_stage = [&](int q, int s) {
        uint32_t stA = sb + s * STAGE_BYTES;
        uint32_t stB = stA + A_BYTES;
        #pragma unroll
        for (int i = 0; i < 8; ++i) {            // A: 1024 chunks / 128 thr
            int c = i * THREADS + tid;
            int r = c >> 3, col = c & 7;
            const __half* src = A + (size_t)(bm + r) * K + q * BKH + col * 8;
            CP16(stA + r * 128 + ((col ^ (r & 7)) * 16), src);
        }
        #pragma unroll
        for (int i = 0; i < 8; ++i) {            // B: 1024 chunks
            int c = i * THREADS + tid;
            int r = c >> 3, col = c & 7;
            const __half* src = BT + (size_t)(bn + r) * K + q * BKH + col * 8;
            CP16(stB + r * 128 + ((col ^ (r & 7)) * 16), src);
        }
    };

    #pragma unroll
    for (int s = 0; s < STAGES - 1; ++s) {
        load_stage(s, s);
        asm volatile("cp.async.commit_group;" ::: "memory");
    }

    for (int q = 0; q < KC; ++q) {
        asm volatile("cp.async.wait_group %0;" :: "n"(STAGES - 2) : "memory");
        __syncthreads();

        int pre = q + STAGES - 1;
        if (pre < KC) load_stage(pre, pre % STAGES);
        asm volatile("cp.async.commit_group;" ::: "memory");

        uint32_t stA = sb + (q % STAGES) * STAGE_BYTES;
        uint32_t stB = stA + A_BYTES;

        // B double-buffered across kk; A loaded in place per kk.
        uint32_t bfr[2][4][4];
        #pragma unroll
        for (int p = 0; p < 4; ++p) {
            int row = brow0 + p * 16;
            LDSM4(bfr[0][p], stB + row * 128 + (((lq & 1) ^ (row & 7)) * 16));
        }

        #pragma unroll
        for (int kk = 0; kk < 4; ++kk) {
            const int cur = kk & 1, nxt = cur ^ 1;
            uint32_t a[4][4];
            #pragma unroll
            for (int mf = 0; mf < 4; ++mf) {
                int row = arow0 + mf * 16;
                int ch  = kk * 2 + (lq >> 1);
                LDSM4(a[mf], stA + row * 128 + ((ch ^ (row & 7)) * 16));
            }
            if (kk < 3) {
                #pragma unroll
                for (int p = 0; p < 4; ++p) {
                    int row = brow0 + p * 16;
                    int ch  = (kk + 1) * 2 + (lq & 1);
                    LDSM4(bfr[nxt][p], stB + row * 128 + ((ch ^ (row & 7)) * 16));
                }
            }
            #pragma unroll
            for (int mf = 0; mf < 4; ++mf)
                #pragma unroll
                for (int p = 0; p < 4; ++p) {
                    MMA16816(acc[mf][2 * p],     a[mf], bfr[cur][p][0], bfr[cur][p][1]);
                    MMA16816(acc[mf][2 * p + 1], a[mf], bfr[cur][p][2], bfr[cur][p][3]);
                }
        }
    }

    if (!FUSE_HEAD) {
        #pragma unroll
        for (int mf = 0; mf < 4; ++mf) {
            int row = bm + wm * 64 + mf * 16 + (lane >> 2);
            #pragma unroll
            for (int nb = 0; nb < 8; ++nb) {
                int col = bn + wn * 64 + nb * 8 + (lane & 3) * 2;
                float bv0 = bias[col], bv1 = bias[col + 1];
                float v0 = fmaxf(acc[mf][nb][0] + bv0, 0.0f);
                float v1 = fmaxf(acc[mf][nb][1] + bv1, 0.0f);
                float v2 = fmaxf(acc[mf][nb][2] + bv0, 0.0f);
                float v3 = fmaxf(acc[mf][nb][3] + bv1, 0.0f);
                *(__half2*)(C + (size_t)row * N + col)       = __floats2half2_rn(v0, v1);
                *(__half2*)(C + (size_t)(row + 8) * N + col) = __floats2half2_rn(v2, v3);
            }
        }
    } else {
        float p0[4], p1[4];
        #pragma unroll
        for (int mf = 0; mf < 4; ++mf) { p0[mf] = 0.f; p1[mf] = 0.f; }
        #pragma unroll
        for (int nb = 0; nb < 8; ++nb) {
            int col = bn + wn * 64 + nb * 8 + (lane & 3) * 2;
            float bv0 = bias[col], bv1 = bias[col + 1];
            float w0 = W3[col],    w1 = W3[col + 1];
            #pragma unroll
            for (int mf = 0; mf < 4; ++mf) {
                p0[mf] += fmaxf(acc[mf][nb][0] + bv0, 0.f) * w0
                        + fmaxf(acc[mf][nb][1] + bv1, 0.f) * w1;
                p1[mf] += fmaxf(acc[mf][nb][2] + bv0, 0.f) * w0
                        + fmaxf(acc[mf][nb][3] + bv1, 0.f) * w1;
            }
        }
        #pragma unroll
        for (int o = 1; o <= 2; o <<= 1)
            #pragma unroll
            for (int mf = 0; mf < 4; ++mf) {
                p0[mf] += __shfl_xor_sync(0xffffffffu, p0[mf], o);
                p1[mf] += __shfl_xor_sync(0xffffffffu, p1[mf], o);
            }
        __syncthreads();                 // mainloop smem dead -> reuse
        float* red = (float*)smem;       // [2][128]
        if ((lane & 3) == 0) {
            #pragma unroll
            for (int mf = 0; mf < 4; ++mf) {
                int rl = wm * 64 + mf * 16 + (lane >> 2);
                red[wn * 128 + rl]     = p0[mf];
                red[wn * 128 + rl + 8] = p1[mf];
            }
        }
        __syncthreads();
        atomicAdd(&out[bm + tid], red[tid] + red[128 + tid]);
    }
}

// ---------------------------------------------------------------- launcher
extern "C" void kernel_launch(void* const* d_in, const int* in_sizes, int n_in,
                              void* d_out, int out_size) {
    const float* h  = (const float*)d_in[0];
    const float* W1 = (const float*)d_in[1];
    const float* b1 = (const float*)d_in[2];
    const float* W2 = (const float*)d_in[3];
    const float* b2 = (const float*)d_in[4];
    const float* W3 = (const float*)d_in[5];
    const float* b3 = (const float*)d_in[6];
    float* out = (float*)d_out;

    __half *feats, *h1, *w1t, *w2t;
    cudaGetSymbolAddress((void**)&feats, g_feats);
    cudaGetSymbolAddress((void**)&h1,    g_h1);
    cudaGetSymbolAddress((void**)&w1t,   g_w1t);
    cudaGetSymbolAddress((void**)&w2t,   g_w2t);

    cudaFuncSetAttribute((const void*)gemm_fp16<false, true>,
        cudaFuncAttributeMaxDynamicSharedMemorySize, SMEM_TOTAL);
    cudaFuncSetAttribute((const void*)gemm_fp16<true, false>,
        cudaFuncAttributeMaxDynamicSharedMemorySize, SMEM_TOTAL);

    // launch 0: fused setup (split prefix + transpose W1)
    setup_kernel<<<SETUP_BLKS, 256>>>(h, W1);

    // launch 1: h1 = relu(feats @ W1 + b1) -> fp16
    //           + trailing blocks: transpose W2 -> g_w2t, out = b3
    gemm_fp16<false, true><<<G1_TOTAL, THREADS, SMEM_TOTAL>>>(
        feats, w1t, b1, h1, nullptr, out, K1_, N1_, W2, b3);

    // launch 2: out += relu(h1 @ W2 + b2) @ W3   (head fused)
    gemm_fp16<true, false><<<dim3(N2_ / BN, M_ / BM), THREADS, SMEM_TOTAL>>>(
        h1, w2t, b2, nullptr, W3, out, K2_, N2_, nullptr, nullptr);
}

// round 16
// speedup vs baseline: 1.0619x; 1.0014x over previous
#include <cuda_runtime.h>
#include <cuda_fp16.h>
#include <cstdint>

// ---------------------------------------------------------------- dims
#define B_  128
#define T_  254
#define D_  768
#define H_  1024
#define M_  (B_ * T_)      // 32512
#define K1_ (2 * D_)       // 1536
#define N1_ (2 * H_)       // 2048
#define K2_ N1_            // 2048
#define N2_ H_             // 1024

// ---------------------------------------------------------------- scratch
__device__ __half g_feats[(size_t)M_ * K1_];   // fp16 features [M,1536]
__device__ __half g_h1[(size_t)M_ * N1_];      // fp16 h1 [M,2048]
__device__ __half g_w1t[(size_t)N1_ * K1_];    // W1^T fp16 [N,K]
__device__ __half g_w2t[(size_t)N2_ * K2_];    // W2^T fp16 [N,K]

// ---------------------------------------------------------------- helpers
__device__ __forceinline__ uint32_t smem_u32(const void* p) {
    uint32_t a;
    asm("{ .reg .u64 t; cvta.to.shared.u64 t, %1; cvt.u32.u64 %0, t; }"
        : "=r"(a) : "l"(p));
    return a;
}

#define CP16(dst, src) \
    asm volatile("cp.async.cg.shared.global [%0], [%1], 16;" \
                 :: "r"(dst), "l"(src) : "memory")

#define LDSM4(r, addr)                                                        \
    asm volatile("ldmatrix.sync.aligned.m8n8.x4.shared.b16 {%0,%1,%2,%3}, [%4];" \
        : "=r"((r)[0]), "=r"((r)[1]), "=r"((r)[2]), "=r"((r)[3]) : "r"(addr))

#define MMA16816(c, a, b0, b1)                                                \
    asm volatile("mma.sync.aligned.m16n8k16.row.col.f32.f16.f16.f32 "         \
        "{%0,%1,%2,%3},{%4,%5,%6,%7},{%8,%9},{%0,%1,%2,%3};"                  \
        : "+f"((c)[0]), "+f"((c)[1]), "+f"((c)[2]), "+f"((c)[3])              \
        : "r"((a)[0]), "r"((a)[1]), "r"((a)[2]), "r"((a)[3]),                 \
          "r"(b0), "r"(b1))

// ---------------------------------------------------------------- shared transpose helper
__device__ __forceinline__ void do_transpose(const float* __restrict__ W,
                                             __half* __restrict__ WT,
                                             int K, int N, int bx, int by, int tid) {
    __shared__ float tile[32][33];
    int k0 = bx * 32, n0 = by * 32;
    int tx = tid & 31, ty = tid >> 5;
    int nty = blockDim.x >> 5;
    for (int j = ty; j < 32; j += nty)
        tile[j][tx] = W[(size_t)(k0 + j) * N + n0 + tx];
    __syncthreads();
    for (int j = ty; j < 32; j += nty)
        WT[(size_t)(n0 + j) * K + k0 + tx] = __float2half_rn(tile[tx][j]);
}

// ---------------------------------------------------------------- fused setup
// [0, 384)     prefix scan, T split in two halves
// [384, +3072) transpose W1 -> g_w1t
#define PFX_BLKS   (B_ * D_ / 2 / 256)                 // 192 per half
#define T1_BX      (K1_ / 32)                          // 48
#define T1_BLKS    (T1_BX * (N1_ / 32))                // 3072
#define SETUP_BLKS (2 * PFX_BLKS + T1_BLKS)            // 3456
#define T_SPLIT 128

__global__ __launch_bounds__(256) void setup_kernel(
    const float* __restrict__ h, const float* __restrict__ W1)
{
    int blk = blockIdx.x;
    int tid = threadIdx.x;

    if (blk < 2 * PFX_BLKS) {
        int half = blk >= PFX_BLKS;
        int idx = (blk - half * PFX_BLKS) * 256 + tid;     // over B_*D_/2
        int b  = idx / (D_ / 2);
        int d2 = idx - b * (D_ / 2);
        const float2* hp = (const float2*)(h + (size_t)b * T_ * D_) + d2;
        __half2* fm = (__half2*)(g_feats + (size_t)b * T_ * K1_) + d2;
        __half2* fx = (__half2*)(g_feats + (size_t)b * T_ * K1_ + D_) + d2;
        float r0 = 0.0f, r1 = 0.0f;
        int t0 = half ? T_SPLIT : 0;
        int t1 = half ? T_ : T_SPLIT;
        if (half) {
            #pragma unroll 1
            for (int t = 0; t < T_SPLIT; t += 8) {
                float2 x[8];
                #pragma unroll
                for (int j = 0; j < 8; ++j) x[j] = hp[(size_t)(t + j) * (D_ / 2)];
                #pragma unroll
                for (int j = 0; j < 8; ++j) { r0 += x[j].x; r1 += x[j].y; }
            }
        }
        int t = t0;
        #pragma unroll 1
        for (; t + 4 <= t1; t += 4) {
            float2 x0 = hp[(size_t)(t + 0) * (D_ / 2)];
            float2 x1 = hp[(size_t)(t + 1) * (D_ / 2)];
            float2 x2 = hp[(size_t)(t + 2) * (D_ / 2)];
            float2 x3 = hp[(size_t)(t + 3) * (D_ / 2)];
            float i0 = 1.0f / (float)(t + 0 > 1 ? t + 0 : 1);
            float i1 = 1.0f / (float)(t + 1 > 1 ? t + 1 : 1);
            float i2 = 1.0f / (float)(t + 2);
            float i3 = 1.0f / (float)(t + 3);
            fm[(size_t)(t + 0) * (K1_ / 2)] = __floats2half2_rn(r0 * i0, r1 * i0);
            fx[(size_t)(t + 0) * (K1_ / 2)] = __floats2half2_rn(x0.x, x0.y);
            r0 += x0.x; r1 += x0.y;
            fm[(size_t)(t + 1) * (K1_ / 2)] = __floats2half2_rn(r0 * i1, r1 * i1);
            fx[(size_t)(t + 1) * (K1_ / 2)] = __floats2half2_rn(x1.x, x1.y);
            r0 += x1.x; r1 += x1.y;
            fm[(size_t)(t + 2) * (K1_ / 2)] = __floats2half2_rn(r0 * i2, r1 * i2);
            fx[(size_t)(t + 2) * (K1_ / 2)] = __floats2half2_rn(x2.x, x2.y);
            r0 += x2.x; r1 += x2.y;
            fm[(size_t)(t + 3) * (K1_ / 2)] = __floats2half2_rn(r0 * i3, r1 * i3);
            fx[(size_t)(t + 3) * (K1_ / 2)] = __floats2half2_rn(x3.x, x3.y);
            r0 += x3.x; r1 += x3.y;
        }
        for (; t < t1; ++t) {
            float2 x = hp[(size_t)t * (D_ / 2)];
            float inv = 1.0f / (float)(t > 1 ? t : 1);
            fm[(size_t)t * (K1_ / 2)] = __floats2half2_rn(r0 * inv, r1 * inv);
            fx[(size_t)t * (K1_ / 2)] = __floats2half2_rn(x.x, x.y);
            r0 += x.x; r1 += x.y;
        }
    } else {
        int t = blk - 2 * PFX_BLKS;
        do_transpose(W1, g_w1t, K1_, N1_, t % T1_BX, t / T1_BX, tid);
    }
}

// ---------------------------------------------------------------- fp16 tensor GEMM
// Tile 128x128, 4 warps (2M x 2N), warp tile 64x64, 3-stage cp.async, 2 CTAs/SM.
// FULL A+B fragment double-buffering across kk. At 128 thr/CTA the reg cap is
// 255 (not 128 as with 256 thr), so acc(128)+afr(32)+bfr(32) fits comfortably.
#define BM 128
#define BN 128
#define BKH 64
#define STAGES 3
#define THREADS 128
#define A_BYTES (BM * 128)
#define STAGE_BYTES (A_BYTES + BN * 128)      // 32768
#define SMEM_TOTAL (STAGES * STAGE_BYTES)     // 98304

#define G1_NX      (N1_ / BN)                 // 16
#define G1_BLKS    (G1_NX * (M_ / BM))        // 4064
#define T2_BX      (K2_ / 32)                 // 64
#define T2_BLKS    (T2_BX * (N2_ / 32))       // 2048
#define INIT_BLKS  ((M_ + THREADS - 1) / THREADS)   // 254
#define G1_TOTAL   (G1_BLKS + T2_BLKS + INIT_BLKS)

template <bool FUSE_HEAD, bool SIDE>
__global__ __launch_bounds__(THREADS, 2) void gemm_fp16(
    const __half* __restrict__ A, const __half* __restrict__ BT,
    const float* __restrict__ bias, __half* __restrict__ C,
    const float* __restrict__ W3, float* __restrict__ out,
    int K, int N,
    const float* __restrict__ Wside, const float* __restrict__ b3)
{
    extern __shared__ char smem[];
    const int tid = threadIdx.x;

    int bx, by;
    if (SIDE) {
        int bid = blockIdx.x;
        if (bid >= G1_BLKS) {
            int t = bid - G1_BLKS;
            if (t < T2_BLKS) {
                do_transpose(Wside, g_w2t, K2_, N2_, t % T2_BX, t / T2_BX, tid);
            } else {
                int i = (t - T2_BLKS) * THREADS + tid;
                if (i < M_) out[i] = b3[0];
            }
            return;
        }
        bx = bid % G1_NX;
        by = bid / G1_NX;
    } else {
        bx = blockIdx.x;
        by = blockIdx.y;
    }

    const uint32_t sb = smem_u32(smem);
    const int warp = tid >> 5;
    const int lane = tid & 31;
    const int wm = warp & 1;          // 2 warps along M (64 rows each)
    const int wn = warp >> 1;         // 2 warps along N (64 cols each)
    const int bm = by * BM;
    const int bn = bx * BN;
    const int KC = K / BKH;
    const int lq = lane >> 3;         // quad 0..3
    const int lr = lane & 7;          // row in quad

    float acc[4][8][4];
    #pragma unroll
    for (int i = 0; i < 4; ++i)
        #pragma unroll
        for (int j = 0; j < 8; ++j)
            #pragma unroll
            for (int c = 0; c < 4; ++c) acc[i][j][c] = 0.0f;

    const int arow0 = wm * 64 + (lq & 1) * 8 + lr;    // + mf*16
    const int brow0 = wn * 64 + (lq >> 1) * 8 + lr;   // + p*16

    auto load_stage = [&](int q, int s) {
        uint32_t stA = sb + s * STAGE_BYTES;
        uint32_t stB = stA + A_BYTES;
        #pragma unroll
        for (int i = 0; i < 8; ++i) {            // A: 1024 chunks / 128 thr
            int c = i * THREADS + tid;
            int r = c >> 3, col = c & 7;
            const __half* src = A + (size_t)(bm + r) * K + q * BKH + col * 8;
            CP16(stA + r * 128 + ((col ^ (r & 7)) * 16), src);
        }
        #pragma unroll
        for (int i = 0; i < 8; ++i) {            // B: 1024 chunks
            int c = i * THREADS + tid;
            int r = c >> 3, col = c & 7;
            const __half* src = BT + (size_t)(bn + r) * K + q * BKH + col * 8;
            CP16(stB + r * 128 + ((col ^ (r & 7)) * 16), src);
        }
    };

    #pragma unroll
    for (int s = 0; s < STAGES - 1; ++s) {
        load_stage(s, s);
        asm volatile("cp.async.commit_group;" ::: "memory");
    }

    for (int q = 0; q < KC; ++q) {
        asm volatile("cp.async.wait_group %0;" :: "n"(STAGES - 2) : "memory");
        __syncthreads();

        int pre = q + STAGES - 1;
        if (pre < KC) load_stage(pre, pre % STAGES);
        asm volatile("cp.async.commit_group;" ::: "memory");

        uint32_t stA = sb + (q % STAGES) * STAGE_BYTES;
        uint32_t stB = stA + A_BYTES;

        // Full A+B double-buffer across kk.
        uint32_t afr[2][4][4], bfr[2][4][4];
        #pragma unroll
        for (int mf = 0; mf < 4; ++mf) {
            int row = arow0 + mf * 16;
            LDSM4(afr[0][mf], stA + row * 128 + (((lq >> 1) ^ (row & 7)) * 16));
        }
        #pragma unroll
        for (int p = 0; p < 4; ++p) {
            int row = brow0 + p * 16;
            LDSM4(bfr[0][p], stB + row * 128 + (((lq & 1) ^ (row & 7)) * 16));
        }

        #pragma unroll
        for (int kk = 0; kk < 4; ++kk) {
            const int cur = kk & 1, nxt = cur ^ 1;
            if (kk < 3) {
                #pragma unroll
                for (int mf = 0; mf < 4; ++mf) {
                    int row = arow0 + mf * 16;
                    int ch  = (kk + 1) * 2 + (lq >> 1);
                    LDSM4(afr[nxt][mf], stA + row * 128 + ((ch ^ (row & 7)) * 16));
                }
                #pragma unroll
                for (int p = 0; p < 4; ++p) {
                    int row = brow0 + p * 16;
                    int ch  = (kk + 1) * 2 + (lq & 1);
                    LDSM4(bfr[nxt][p], stB + row * 128 + ((ch ^ (row & 7)) * 16));
                }
            }
            #pragma unroll
            for (int mf = 0; mf < 4; ++mf)
                #pragma unroll
                for (int p = 0; p < 4; ++p) {
                    MMA16816(acc[mf][2 * p],     afr[cur][mf], bfr[cur][p][0], bfr[cur][p][1]);
                    MMA16816(acc[mf][2 * p + 1], afr[cur][mf], bfr[cur][p][2], bfr[cur][p][3]);
                }
        }
    }

    if (!FUSE_HEAD) {
        #pragma unroll
        for (int mf = 0; mf < 4; ++mf) {
            int row = bm + wm * 64 + mf * 16 + (lane >> 2);
            #pragma unroll
            for (int nb = 0; nb < 8; ++nb) {
                int col = bn + wn * 64 + nb * 8 + (lane & 3) * 2;
                float bv0 = bias[col], bv1 = bias[col + 1];
                float v0 = fmaxf(acc[mf][nb][0] + bv0, 0.0f);
                float v1 = fmaxf(acc[mf][nb][1] + bv1, 0.0f);
                float v2 = fmaxf(acc[mf][nb][2] + bv0, 0.0f);
                float v3 = fmaxf(acc[mf][nb][3] + bv1, 0.0f);
                *(__half2*)(C + (size_t)row * N + col)       = __floats2half2_rn(v0, v1);
                *(__half2*)(C + (size_t)(row + 8) * N + col) = __floats2half2_rn(v2, v3);
            }
        }
    } else {
        float p0[4], p1[4];
        #pragma unroll
        for (int mf = 0; mf < 4; ++mf) { p0[mf] = 0.f; p1[mf] = 0.f; }
        #pragma unroll
        for (int nb = 0; nb < 8; ++nb) {
            int col = bn + wn * 64 + nb * 8 + (lane & 3) * 2;
            float bv0 = bias[col], bv1 = bias[col + 1];
            float w0 = W3[col],    w1 = W3[col + 1];
            #pragma unroll
            for (int mf = 0; mf < 4; ++mf) {
                p0[mf] += fmaxf(acc[mf][nb][0] + bv0, 0.f) * w0
                        + fmaxf(acc[mf][nb][1] + bv1, 0.f) * w1;
                p1[mf] += fmaxf(acc[mf][nb][2] + bv0, 0.f) * w0
                        + fmaxf(acc[mf][nb][3] + bv1, 0.f) * w1;
            }
        }
        #pragma unroll
        for (int o = 1; o <= 2; o <<= 1)
            #pragma unroll
            for (int mf = 0; mf < 4; ++mf) {
                p0[mf] += __shfl_xor_sync(0xffffffffu, p0[mf], o);
                p1[mf] += __shfl_xor_sync(0xffffffffu, p1[mf], o);
            }
        __syncthreads();                 // mainloop smem dead -> reuse
        float* red = (float*)smem;       // [2][128]
        if ((lane & 3) == 0) {
            #pragma unroll
            for (int mf = 0; mf < 4; ++mf) {
                int rl = wm * 64 + mf * 16 + (lane >> 2);
                red[wn * 128 + rl]     = p0[mf];
                red[wn * 128 + rl + 8] = p1[mf];
            }
        }
        __syncthreads();
        atomicAdd(&out[bm + tid], red[tid] + red[128 + tid]);
    }
}

// ---------------------------------------------------------------- launcher
extern "C" void kernel_launch(void* const* d_in, const int* in_sizes, int n_in,
                              void* d_out, int out_size) {
    const float* h  = (const float*)d_in[0];
    const float* W1 = (const float*)d_in[1];
    const float* b1 = (const float*)d_in[2];
    const float* W2 = (const float*)d_in[3];
    const float* b2 = (const float*)d_in[4];
    const float* W3 = (const float*)d_in[5];
    const float* b3 = (const float*)d_in[6];
    float* out = (float*)d_out;

    __half *feats, *h1, *w1t, *w2t;
    cudaGetSymbolAddress((void**)&feats, g_feats);
    cudaGetSymbolAddress((void**)&h1,    g_h1);
    cudaGetSymbolAddress((void**)&w1t,   g_w1t);
    cudaGetSymbolAddress((void**)&w2t,   g_w2t);

    cudaFuncSetAttribute((const void*)gemm_fp16<false, true>,
        cudaFuncAttributeMaxDynamicSharedMemorySize, SMEM_TOTAL);
    cudaFuncSetAttribute((const void*)gemm_fp16<true, false>,
        cudaFuncAttributeMaxDynamicSharedMemorySize, SMEM_TOTAL);

    // launch 0: fused setup (split prefix + transpose W1)
    setup_kernel<<<SETUP_BLKS, 256>>>(h, W1);

    // launch 1: h1 = relu(feats @ W1 + b1) -> fp16
    //           + trailing blocks: transpose W2 -> g_w2t, out = b3
    gemm_fp16<false, true><<<G1_TOTAL, THREADS, SMEM_TOTAL>>>(
        feats, w1t, b1, h1, nullptr, out, K1_, N1_, W2, b3);

    // launch 2: out += relu(h1 @ W2 + b2) @ W3   (head fused)
    gemm_fp16<true, false><<<dim3(N2_ / BN, M_ / BM), THREADS, SMEM_TOTAL>>>(
        h1, w2t, b2, nullptr, W3, out, K2_, N2_, nullptr, nullptr);
}

// round 17
// speedup vs baseline: 1.0751x; 1.0125x over previous
#include <cuda_runtime.h>
#include <cuda_fp16.h>
#include <cstdint>

// ---------------------------------------------------------------- dims
#define B_  128
#define T_  254
#define D_  768
#define H_  1024
#define M_  (B_ * T_)      // 32512
#define K1_ (2 * D_)       // 1536
#define N1_ (2 * H_)       // 2048
#define K2_ N1_            // 2048
#define N2_ H_             // 1024

// ---------------------------------------------------------------- scratch
__device__ __half g_feats[(size_t)M_ * K1_];   // fp16 features [M,1536]
__device__ __half g_h1[(size_t)M_ * N1_];      // fp16 h1 [M,2048]
__device__ __half g_w1t[(size_t)N1_ * K1_];    // W1^T fp16 [N,K]
__device__ __half g_w2t[(size_t)N2_ * K2_];    // W2^T fp16 [N,K]

// ---------------------------------------------------------------- helpers
__device__ __forceinline__ uint32_t smem_u32(const void* p) {
    uint32_t a;
    asm("{ .reg .u64 t; cvta.to.shared.u64 t, %1; cvt.u32.u64 %0, t; }"
        : "=r"(a) : "l"(p));
    return a;
}

#define CP16(dst, src) \
    asm volatile("cp.async.cg.shared.global [%0], [%1], 16;" \
                 :: "r"(dst), "l"(src) : "memory")

#define LDSM4(r, addr)                                                        \
    asm volatile("ldmatrix.sync.aligned.m8n8.x4.shared.b16 {%0,%1,%2,%3}, [%4];" \
        : "=r"((r)[0]), "=r"((r)[1]), "=r"((r)[2]), "=r"((r)[3]) : "r"(addr))

#define MMA16816(c, a, b0, b1)                                                \
    asm volatile("mma.sync.aligned.m16n8k16.row.col.f32.f16.f16.f32 "         \
        "{%0,%1,%2,%3},{%4,%5,%6,%7},{%8,%9},{%0,%1,%2,%3};"                  \
        : "+f"((c)[0]), "+f"((c)[1]), "+f"((c)[2]), "+f"((c)[3])              \
        : "r"((a)[0]), "r"((a)[1]), "r"((a)[2]), "r"((a)[3]),                 \
          "r"(b0), "r"(b1))

// ---------------------------------------------------------------- shared transpose helper
__device__ __forceinline__ void do_transpose(const float* __restrict__ W,
                                             __half* __restrict__ WT,
                                             int K, int N, int bx, int by, int tid) {
    __shared__ float tile[32][33];
    int k0 = bx * 32, n0 = by * 32;
    int tx = tid & 31, ty = tid >> 5;
    int nty = blockDim.x >> 5;
    for (int j = ty; j < 32; j += nty)
        tile[j][tx] = W[(size_t)(k0 + j) * N + n0 + tx];
    __syncthreads();
    for (int j = ty; j < 32; j += nty)
        WT[(size_t)(n0 + j) * K + k0 + tx] = __float2half_rn(tile[tx][j]);
}

// ---------------------------------------------------------------- fused setup
// Prefix scan split into 4 T-chunks (serial chain ~64; chunks re-accumulate
// their base sum with MLP-8 reads that hit L2 — h fits in the 126MB L2).
// [0, 768)      prefix chunks
// [768, +3072)  transpose W1 -> g_w1t
#define PFX_BLKS   (B_ * D_ / 2 / 256)                 // 192 per chunk
#define N_CHUNK    4
#define CHUNK_T    64                                  // 4*64 >= 254
#define T1_BX      (K1_ / 32)                          // 48
#define T1_BLKS    (T1_BX * (N1_ / 32))                // 3072
#define SETUP_BLKS (N_CHUNK * PFX_BLKS + T1_BLKS)      // 3840

__global__ __launch_bounds__(256) void setup_kernel(
    const float* __restrict__ h, const float* __restrict__ W1)
{
    int blk = blockIdx.x;
    int tid = threadIdx.x;

    if (blk < N_CHUNK * PFX_BLKS) {
        int chunk = blk / PFX_BLKS;
        int idx = (blk - chunk * PFX_BLKS) * 256 + tid;    // over B_*D_/2
        int b  = idx / (D_ / 2);
        int d2 = idx - b * (D_ / 2);
        const float2* hp = (const float2*)(h + (size_t)b * T_ * D_) + d2;
        __half2* fm = (__half2*)(g_feats + (size_t)b * T_ * K1_) + d2;
        __half2* fx = (__half2*)(g_feats + (size_t)b * T_ * K1_ + D_) + d2;
        float r0 = 0.0f, r1 = 0.0f;
        int t0 = chunk * CHUNK_T;
        int t1 = (chunk == N_CHUNK - 1) ? T_ : (t0 + CHUNK_T);
        // re-accumulate base sum over [0, t0): batched MLP-8 reads (L2 hits)
        #pragma unroll 1
        for (int t = 0; t < t0; t += 8) {
            float2 x[8];
            #pragma unroll
            for (int j = 0; j < 8; ++j) x[j] = hp[(size_t)(t + j) * (D_ / 2)];
            #pragma unroll
            for (int j = 0; j < 8; ++j) { r0 += x[j].x; r1 += x[j].y; }
        }
        // scan [t0, t1), unroll 8 (batched loads, then compute+store)
        int t = t0;
        #pragma unroll 1
        for (; t + 8 <= t1; t += 8) {
            float2 x[8];
            #pragma unroll
            for (int j = 0; j < 8; ++j) x[j] = hp[(size_t)(t + j) * (D_ / 2)];
            #pragma unroll
            for (int j = 0; j < 8; ++j) {
                int tj = t + j;
                float inv = 1.0f / (float)(tj > 1 ? tj : 1);
                fm[(size_t)tj * (K1_ / 2)] = __floats2half2_rn(r0 * inv, r1 * inv);
                fx[(size_t)tj * (K1_ / 2)] = __floats2half2_rn(x[j].x, x[j].y);
                r0 += x[j].x; r1 += x[j].y;
            }
        }
        for (; t < t1; ++t) {
            float2 x = hp[(size_t)t * (D_ / 2)];
            float inv = 1.0f / (float)(t > 1 ? t : 1);
            fm[(size_t)t * (K1_ / 2)] = __floats2half2_rn(r0 * inv, r1 * inv);
            fx[(size_t)t * (K1_ / 2)] = __floats2half2_rn(x.x, x.y);
            r0 += x.x; r1 += x.y;
        }
    } else {
        int t = blk - N_CHUNK * PFX_BLKS;
        do_transpose(W1, g_w1t, K1_, N1_, t % T1_BX, t / T1_BX, tid);
    }
}

// ---------------------------------------------------------------- fp16 tensor GEMM
// Tile 128x128, 4 warps (2M x 2N), warp tile 64x64, 3-stage cp.async, 2 CTAs/SM.
// Full A+B fragment double-buffering across kk (R16 mainloop, frozen).
#define BM 128
#define BN 128
#define BKH 64
#define STAGES 3
#define THREADS 128
#define A_BYTES (BM * 128)
#define STAGE_BYTES (A_BYTES + BN * 128)      // 32768
#define SMEM_TOTAL (STAGES * STAGE_BYTES)     // 98304

#define G1_NX      (N1_ / BN)                 // 16
#define G1_BLKS    (G1_NX * (M_ / BM))        // 4064
#define T2_BX      (K2_ / 32)                 // 64
#define T2_BLKS    (T2_BX * (N2_ / 32))       // 2048
#define INIT_BLKS  ((M_ + THREADS - 1) / THREADS)   // 254
#define G1_TOTAL   (G1_BLKS + T2_BLKS + INIT_BLKS)

template <bool FUSE_HEAD, bool SIDE>
__global__ __launch_bounds__(THREADS, 2) void gemm_fp16(
    const __half* __restrict__ A, const __half* __restrict__ BT,
    const float* __restrict__ bias, __half* __restrict__ C,
    const float* __restrict__ W3, float* __restrict__ out,
    int K, int N,
    const float* __restrict__ Wside, const float* __restrict__ b3)
{
    extern __shared__ char smem[];
    const int tid = threadIdx.x;

    int bx, by;
    if (SIDE) {
        int bid = blockIdx.x;
        if (bid >= G1_BLKS) {
            int t = bid - G1_BLKS;
            if (t < T2_BLKS) {
                do_transpose(Wside, g_w2t, K2_, N2_, t % T2_BX, t / T2_BX, tid);
            } else {
                int i = (t - T2_BLKS) * THREADS + tid;
                if (i < M_) out[i] = b3[0];
            }
            return;
        }
        bx = bid % G1_NX;
        by = bid / G1_NX;
    } else {
        bx = blockIdx.x;
        by = blockIdx.y;
    }

    const uint32_t sb = smem_u32(smem);
    const int warp = tid >> 5;
    const int lane = tid & 31;
    const int wm = warp & 1;          // 2 warps along M (64 rows each)
    const int wn = warp >> 1;         // 2 warps along N (64 cols each)
    const int bm = by * BM;
    const int bn = bx * BN;
    const int KC = K / BKH;
    const int lq = lane >> 3;         // quad 0..3
    const int lr = lane & 7;          // row in quad

    float acc[4][8][4];
    #pragma unroll
    for (int i = 0; i < 4; ++i)
        #pragma unroll
        for (int j = 0; j < 8; ++j)
            #pragma unroll
            for (int c = 0; c < 4; ++c) acc[i][j][c] = 0.0f;

    const int arow0 = wm * 64 + (lq & 1) * 8 + lr;    // + mf*16
    const int brow0 = wn * 64 + (lq >> 1) * 8 + lr;   // + p*16

    auto load_stage = [&](int q, int s) {
        uint32_t stA = sb + s * STAGE_BYTES;
        uint32_t stB = stA + A_BYTES;
        #pragma unroll
        for (int i = 0; i < 8; ++i) {            // A: 1024 chunks / 128 thr
            int c = i * THREADS + tid;
            int r = c >> 3, col = c & 7;
            const __half* src = A + (size_t)(bm + r) * K + q * BKH + col * 8;
            CP16(stA + r * 128 + ((col ^ (r & 7)) * 16), src);
        }
        #pragma unroll
        for (int i = 0; i < 8; ++i) {            // B: 1024 chunks
            int c = i * THREADS + tid;
            int r = c >> 3, col = c & 7;
            const __half* src = BT + (size_t)(bn + r) * K + q * BKH + col * 8;
            CP16(stB + r * 128 + ((col ^ (r & 7)) * 16), src);
        }
    };

    #pragma unroll
    for (int s = 0; s < STAGES - 1; ++s) {
        load_stage(s, s);
        asm volatile("cp.async.commit_group;" ::: "memory");
    }

    for (int q = 0; q < KC; ++q) {
        asm volatile("cp.async.wait_group %0;" :: "n"(STAGES - 2) : "memory");
        __syncthreads();

        int pre = q + STAGES - 1;
        if (pre < KC) load_stage(pre, pre % STAGES);
        asm volatile("cp.async.commit_group;" ::: "memory");

        uint32_t stA = sb + (q % STAGES) * STAGE_BYTES;
        uint32_t stB = stA + A_BYTES;

        // Full A+B double-buffer across kk.
        uint32_t afr[2][4][4], bfr[2][4][4];
        #pragma unroll
        for (int mf = 0; mf < 4; ++mf) {
            int row = arow0 + mf * 16;
            LDSM4(afr[0][mf], stA + row * 128 + (((lq >> 1) ^ (row & 7)) * 16));
        }
        #pragma unroll
        for (int p = 0; p < 4; ++p) {
            int row = brow0 + p * 16;
            LDSM4(bfr[0][p], stB + row * 128 + (((lq & 1) ^ (row & 7)) * 16));
        }

        #pragma unroll
        for (int kk = 0; kk < 4; ++kk) {
            const int cur = kk & 1, nxt = cur ^ 1;
            if (kk < 3) {
                #pragma unroll
                for (int mf = 0; mf < 4; ++mf) {
                    int row = arow0 + mf * 16;
                    int ch  = (kk + 1) * 2 + (lq >> 1);
                    LDSM4(afr[nxt][mf], stA + row * 128 + ((ch ^ (row & 7)) * 16));
                }
                #pragma unroll
                for (int p = 0; p < 4; ++p) {
                    int row = brow0 + p * 16;
                    int ch  = (kk + 1) * 2 + (lq & 1);
                    LDSM4(bfr[nxt][p], stB + row * 128 + ((ch ^ (row & 7)) * 16));
                }
            }
            #pragma unroll
            for (int mf = 0; mf < 4; ++mf)
                #pragma unroll
                for (int p = 0; p < 4; ++p) {
                    MMA16816(acc[mf][2 * p],     afr[cur][mf], bfr[cur][p][0], bfr[cur][p][1]);
                    MMA16816(acc[mf][2 * p + 1], afr[cur][mf], bfr[cur][p][2], bfr[cur][p][3]);
                }
        }
    }

    if (!FUSE_HEAD) {
        #pragma unroll
        for (int mf = 0; mf < 4; ++mf) {
            int row = bm + wm * 64 + mf * 16 + (lane >> 2);
            #pragma unroll
            for (int nb = 0; nb < 8; ++nb) {
                int col = bn + wn * 64 + nb * 8 + (lane & 3) * 2;
                float bv0 = bias[col], bv1 = bias[col + 1];
                float v0 = fmaxf(acc[mf][nb][0] + bv0, 0.0f);
                float v1 = fmaxf(acc[mf][nb][1] + bv1, 0.0f);
                float v2 = fmaxf(acc[mf][nb][2] + bv0, 0.0f);
                float v3 = fmaxf(acc[mf][nb][3] + bv1, 0.0f);
                *(__half2*)(C + (size_t)row * N + col)       = __floats2half2_rn(v0, v1);
                *(__half2*)(C + (size_t)(row + 8) * N + col) = __floats2half2_rn(v2, v3);
            }
        }
    } else {
        float p0[4], p1[4];
        #pragma unroll
        for (int mf = 0; mf < 4; ++mf) { p0[mf] = 0.f; p1[mf] = 0.f; }
        #pragma unroll
        for (int nb = 0; nb < 8; ++nb) {
            int col = bn + wn * 64 + nb * 8 + (lane & 3) * 2;
            float bv0 = bias[col], bv1 = bias[col + 1];
            float w0 = W3[col],    w1 = W3[col + 1];
            #pragma unroll
            for (int mf = 0; mf < 4; ++mf) {
                p0[mf] += fmaxf(acc[mf][nb][0] + bv0, 0.f) * w0
                        + fmaxf(acc[mf][nb][1] + bv1, 0.f) * w1;
                p1[mf] += fmaxf(acc[mf][nb][2] + bv0, 0.f) * w0
                        + fmaxf(acc[mf][nb][3] + bv1, 0.f) * w1;
            }
        }
        #pragma unroll
        for (int o = 1; o <= 2; o <<= 1)
            #pragma unroll
            for (int mf = 0; mf < 4; ++mf) {
                p0[mf] += __shfl_xor_sync(0xffffffffu, p0[mf], o);
                p1[mf] += __shfl_xor_sync(0xffffffffu, p1[mf], o);
            }
        __syncthreads();                 // mainloop smem dead -> reuse
        float* red = (float*)smem;       // [2][128]
        if ((lane & 3) == 0) {
            #pragma unroll
            for (int mf = 0; mf < 4; ++mf) {
                int rl = wm * 64 + mf * 16 + (lane >> 2);
                red[wn * 128 + rl]     = p0[mf];
                red[wn * 128 + rl + 8] = p1[mf];
            }
        }
        __syncthreads();
        atomicAdd(&out[bm + tid], red[tid] + red[128 + tid]);
    }
}

// ---------------------------------------------------------------- launcher
extern "C" void kernel_launch(void* const* d_in, const int* in_sizes, int n_in,
                              void* d_out, int out_size) {
    const float* h  = (const float*)d_in[0];
    const float* W1 = (const float*)d_in[1];
    const float* b1 = (const float*)d_in[2];
    const float* W2 = (const float*)d_in[3];
    const float* b2 = (const float*)d_in[4];
    const float* W3 = (const float*)d_in[5];
    const float* b3 = (const float*)d_in[6];
    float* out = (float*)d_out;

    __half *feats, *h1, *w1t, *w2t;
    cudaGetSymbolAddress((void**)&feats, g_feats);
    cudaGetSymbolAddress((void**)&h1,    g_h1);
    cudaGetSymbolAddress((void**)&w1t,   g_w1t);
    cudaGetSymbolAddress((void**)&w2t,   g_w2t);

    cudaFuncSetAttribute((const void*)gemm_fp16<false, true>,
        cudaFuncAttributeMaxDynamicSharedMemorySize, SMEM_TOTAL);
    cudaFuncSetAttribute((const void*)gemm_fp16<true, false>,
        cudaFuncAttributeMaxDynamicSharedMemorySize, SMEM_TOTAL);

    // launch 0: fused setup (4-way split prefix + transpose W1)
    setup_kernel<<<SETUP_BLKS, 256>>>(h, W1);

    // launch 1: h1 = relu(feats @ W1 + b1) -> fp16
    //           + trailing blocks: transpose W2 -> g_w2t, out = b3
    gemm_fp16<false, true><<<G1_TOTAL, THREADS, SMEM_TOTAL>>>(
        feats, w1t, b1, h1, nullptr, out, K1_, N1_, W2, b3);

    // launch 2: out += relu(h1 @ W2 + b2) @ W3   (head fused)
    gemm_fp16<true, false><<<dim3(N2_ / BN, M_ / BM), THREADS, SMEM_TOTAL>>>(
        h1, w2t, b2, nullptr, W3, out, K2_, N2_, nullptr, nullptr);
}